// round 13
// baseline (speedup 1.0000x reference)
#include <cuda_runtime.h>
#include <stdint.h>
#include <float.h>

#define N_ROWS   32768
#define K_CODES  8192
#define DIM      64
#define TH       256
#define BM       128
#define NT       128          // tiles of 64 codes
#define NE       24           // exact (fp32) codes per tile
#define NA       40           // approx (dp4a) codes per tile

// ---- dynamic smem offsets (bytes) ----
#define OFF_XS   0            // float2 xs[128][33]            33792
#define OFF_SX   33792        // float  sxs[128]                 512
#define OFF_XQ   34304        // int2   xq[128][17]            17408
#define OFF_BUF  51712        // 2 x (6144 exact + 5120 packed) = 22528
#define BUF_B    11264
#define SMEM_SZ  (OFF_BUF + 2 * BUF_B)   // 74240

// ---- device globals ----
__device__ int4  g_cq[K_CODES * 8];   // per code: 8 x int4 = 16 (hi4,lo4) groups
__device__ float g_csq[K_CODES];
__device__ float g_scd64[K_CODES];    // sc/64
__device__ int   g_scmax_i;           // atomicMax of sc (as positive-float bits)
__device__ int   g_fixcount;
__device__ int   g_fixlist[N_ROWS];

__device__ __forceinline__ int pack4(int b0, int b1, int b2, int b3) {
    return (b0 & 0xff) | ((b1 & 0xff) << 8) | ((b2 & 0xff) << 16) | ((b3 & 0xff) << 24);
}
__device__ __forceinline__ uint32_t smem_u32(const void* p) {
    uint32_t a;
    asm("{ .reg .u64 t; cvta.to.shared.u64 t, %1; cvt.u32.u64 %0, t; }" : "=r"(a) : "l"(p));
    return a;
}
__device__ __forceinline__ void cp16(uint32_t dst, const void* src) {
    asm volatile("cp.async.ca.shared.global [%0], [%1], 16;" :: "r"(dst), "l"(src) : "memory");
}
#define CP_COMMIT() asm volatile("cp.async.commit_group;" ::: "memory")
#define CP_WAIT1()  asm volatile("cp.async.wait_group 1;" ::: "memory")
#define CP_WAIT0()  asm volatile("cp.async.wait_group 0;" ::: "memory")

// ---------------- pack codebook: int8 2-level split + csq + sc ----------------
__global__ void pack_cb_kernel(const float* __restrict__ cb) {
    int code = blockIdx.x * blockDim.x + threadIdx.x;
    if (code == 0) g_fixcount = 0;
    if (code >= K_CODES) return;
    float f[DIM];
    const float4* c4 = reinterpret_cast<const float4*>(cb + (size_t)code * DIM);
#pragma unroll
    for (int i = 0; i < DIM / 4; i++) *reinterpret_cast<float4*>(f + 4 * i) = c4[i];
    float s = 0.f, mx = 0.f;
#pragma unroll
    for (int d = 0; d < DIM; d++) { s = fmaf(f[d], f[d], s); mx = fmaxf(mx, fabsf(f[d])); }
    float sc = fmaxf(mx, 1e-30f) * (1.0f / 127.0f);
    float q  = 1.0f / sc;
#pragma unroll
    for (int h = 0; h < 8; h++) {
        int hi[8], lo[8];
#pragma unroll
        for (int t = 0; t < 8; t++) {
            float v = f[8 * h + t] * q;
            int ih = __float2int_rn(v);
            hi[t] = ih;
            lo[t] = __float2int_rn((v - (float)ih) * 128.0f);
        }
        g_cq[code * 8 + h] = make_int4(pack4(hi[0], hi[1], hi[2], hi[3]),
                                       pack4(lo[0], lo[1], lo[2], lo[3]),
                                       pack4(hi[4], hi[5], hi[6], hi[7]),
                                       pack4(lo[4], lo[5], lo[6], lo[7]));
    }
    g_csq[code]   = s;
    g_scd64[code] = sc * (1.0f / 64.0f);
    atomicMax(&g_scmax_i, __float_as_int(sc));
}

// ---------------- main dual-pipe kernel ----------------
__device__ __forceinline__ void fill_tile(int t, uint32_t bufb, int tid,
                                          const float* __restrict__ cb) {
    // exact fp32 tile: 24 codes x 256B = 384 x 16B chunks
    {
        int c = tid >> 4, q = tid & 15;
        cp16(bufb + c * 256 + q * 16, cb + (size_t)(t * 64 + c) * DIM + q * 4);
    }
    {
        int idx = tid + 256;
        if (idx < 384) {
            int c = idx >> 4, q = idx & 15;
            cp16(bufb + c * 256 + q * 16, cb + (size_t)(t * 64 + c) * DIM + q * 4);
        }
    }
    // approx packed tile: 40 codes x 128B = 320 x 16B chunks
    {
        int c = tid >> 3, h = tid & 7;   // tid<256 -> c<32
        cp16(bufb + 6144 + c * 128 + h * 16, g_cq + (size_t)(t * 64 + NE + c) * 8 + h);
    }
    {
        int idx = tid + 256;
        if (idx < 320) {
            int c = idx >> 3, h = idx & 7;
            cp16(bufb + 6144 + c * 128 + h * 16, g_cq + (size_t)(t * 64 + NE + c) * 8 + h);
        }
    }
}

__global__ __launch_bounds__(TH, 2)
void vq_kernel(const float* __restrict__ x,
               const float* __restrict__ cb,
               float* __restrict__ out) {
    extern __shared__ char smem[];
    float2* xs  = reinterpret_cast<float2*>(smem + OFF_XS);
    float*  sxs = reinterpret_cast<float*>(smem + OFF_SX);
    int2*   xq  = reinterpret_cast<int2*>(smem + OFF_XQ);
    const uint32_t bufbase = smem_u32(smem) + OFF_BUF;

    const int tid  = threadIdx.x;
    const int lane = tid & 31;
    const int wid  = tid >> 5;
    const int gn0  = blockIdx.x * BM;

    // ---- phase 1: fill x fp32 tile (coalesced) ----
    {
        const float2* gx = reinterpret_cast<const float2*>(x + (size_t)gn0 * DIM);
#pragma unroll
        for (int u = 0; u < (BM * 32) / TH; u++) {
            int idx = u * TH + tid;
            xs[(idx >> 5) * 33 + (idx & 31)] = gx[idx];
        }
    }
    __syncthreads();

    // ---- phase 2: quantize x rows (2 threads per row) ----
    {
        int qrow = tid >> 1, qh = tid & 1;
        const float2* xrow = xs + qrow * 33 + qh * 16;
        float2 xv[16];
        float mx = 0.f;
#pragma unroll
        for (int p = 0; p < 16; p++) {
            xv[p] = xrow[p];
            mx = fmaxf(mx, fmaxf(fabsf(xv[p].x), fabsf(xv[p].y)));
        }
        mx = fmaxf(mx, __shfl_xor_sync(0xffffffffu, mx, 1));
        float sx = fmaxf(mx, 1e-30f) * (1.0f / 127.0f);
        float qs = 1.0f / sx;
        if (qh == 0) sxs[qrow] = sx;
#pragma unroll
        for (int g = 0; g < 8; g++) {
            float v0 = xv[2 * g].x * qs,     v1 = xv[2 * g].y * qs;
            float v2 = xv[2 * g + 1].x * qs, v3 = xv[2 * g + 1].y * qs;
            int h0 = __float2int_rn(v0), h1 = __float2int_rn(v1);
            int h2 = __float2int_rn(v2), h3 = __float2int_rn(v3);
            int l0 = __float2int_rn((v0 - (float)h0) * 128.0f);
            int l1 = __float2int_rn((v1 - (float)h1) * 128.0f);
            int l2 = __float2int_rn((v2 - (float)h2) * 128.0f);
            int l3 = __float2int_rn((v3 - (float)h3) * 128.0f);
            xq[qrow * 17 + qh * 8 + g] = make_int2(pack4(h0, h1, h2, h3),
                                                   pack4(l0, l1, l2, l3));
        }
    }
    __syncthreads();

    // running (best, second, idx); exact warps use [0..3], approx use [0..1]
    float v1[4] = {FLT_MAX, FLT_MAX, FLT_MAX, FLT_MAX};
    float v2[4] = {FLT_MAX, FLT_MAX, FLT_MAX, FLT_MAX};
    int   i1[4] = {0, 0, 0, 0};

    // approx-warp row assignment
    const int rbase = (wid >= 6) ? 64 : 0;
    const int ar0 = rbase + lane, ar1 = ar0 + 32;
    const int cw0 = (wid & 1) * 20;            // approx code sub-range within tile
    const int ec0 = wid * 6;                   // exact code sub-range within tile

    // ---- stage tile 0 ----
    fill_tile(0, bufbase, tid, cb);
    CP_COMMIT();

    for (int t = 0; t < NT; t++) {
        const int s = t & 1;
        if (t) __syncthreads();                // everyone done reading buf[s^1]
        if (t + 1 < NT) {
            fill_tile(t + 1, bufbase + (s ^ 1) * BUF_B, tid, cb);
            CP_COMMIT();
            CP_WAIT1();
        } else {
            CP_WAIT0();
        }
        __syncthreads();                       // tile t visible

        if (wid < 4) {
            // ======== exact fp32 path (fma pipe) ========
            const float2* cs = reinterpret_cast<const float2*>(smem + OFF_BUF + s * BUF_B);
            float acc[4][6];
#pragma unroll
            for (int i = 0; i < 4; i++)
#pragma unroll
                for (int j = 0; j < 6; j++) acc[i][j] = 0.f;
#pragma unroll 8
            for (int p = 0; p < 32; p++) {
                float2 a0 = xs[lane * 33 + p];
                float2 a1 = xs[(lane + 32) * 33 + p];
                float2 a2 = xs[(lane + 64) * 33 + p];
                float2 a3 = xs[(lane + 96) * 33 + p];
                float2 b[6];
#pragma unroll
                for (int j = 0; j < 6; j++) b[j] = cs[(ec0 + j) * 32 + p];
#pragma unroll
                for (int j = 0; j < 6; j++) {
                    acc[0][j] = fmaf(a0.x, b[j].x, acc[0][j]); acc[0][j] = fmaf(a0.y, b[j].y, acc[0][j]);
                    acc[1][j] = fmaf(a1.x, b[j].x, acc[1][j]); acc[1][j] = fmaf(a1.y, b[j].y, acc[1][j]);
                    acc[2][j] = fmaf(a2.x, b[j].x, acc[2][j]); acc[2][j] = fmaf(a2.y, b[j].y, acc[2][j]);
                    acc[3][j] = fmaf(a3.x, b[j].x, acc[3][j]); acc[3][j] = fmaf(a3.y, b[j].y, acc[3][j]);
                }
            }
#pragma unroll
            for (int j = 0; j < 6; j++) {
                int gk = t * 64 + ec0 + j;
                float cqv = __ldg(&g_csq[gk]);
#pragma unroll
                for (int i = 0; i < 4; i++) {
                    float d = fmaf(-2.f, acc[i][j], cqv);
                    if (d < v1[i]) { v2[i] = v1[i]; v1[i] = d; i1[i] = gk; }
                    else if (d < v2[i]) v2[i] = d;
                }
            }
        } else {
            // ======== approx int8 path (alu pipe, dp4a) ========
            const int2* dq = reinterpret_cast<const int2*>(smem + OFF_BUF + s * BUF_B + 6144);
            int2 X0[16], X1[16];
#pragma unroll
            for (int g = 0; g < 16; g++) {
                X0[g] = xq[ar0 * 17 + g];
                X1[g] = xq[ar1 * 17 + g];
            }
            float sx0 = sxs[ar0], sx1 = sxs[ar1];
#pragma unroll 2
            for (int c = 0; c < 20; c++) {
                const int cc = cw0 + c;
                int hh0 = 0, hl0 = 0, lh0 = 0, hh1 = 0, hl1 = 0, lh1 = 0;
#pragma unroll
                for (int g = 0; g < 16; g++) {
                    int2 cg = dq[cc * 16 + g];
                    hh0 = __dp4a(X0[g].x, cg.x, hh0);
                    hl0 = __dp4a(X0[g].x, cg.y, hl0);
                    lh0 = __dp4a(X0[g].y, cg.x, lh0);
                    hh1 = __dp4a(X1[g].x, cg.x, hh1);
                    hl1 = __dp4a(X1[g].x, cg.y, hl1);
                    lh1 = __dp4a(X1[g].y, cg.x, lh1);
                }
                int gk = t * 64 + NE + cc;
                float cqv = __ldg(&g_csq[gk]);
                float cK  = __ldg(&g_scd64[gk]);
                float f0 = (float)(hh0 * 128 + hl0 + lh0);
                float f1 = (float)(hh1 * 128 + hl1 + lh1);
                float d0 = fmaf(-cK * sx0, f0, cqv);
                float d1 = fmaf(-cK * sx1, f1, cqv);
                if (d0 < v1[0]) { v2[0] = v1[0]; v1[0] = d0; i1[0] = gk; }
                else if (d0 < v2[0]) v2[0] = d0;
                if (d1 < v1[1]) { v2[1] = v1[1]; v1[1] = d1; i1[1] = gk; }
                else if (d1 < v2[1]) v2[1] = d1;
            }
        }
    }

    // ---- final reduction: 6 contributors per row (4 exact warps + 2 approx) ----
    __syncthreads();                           // safe to overlay buffers
    float* rv = reinterpret_cast<float*>(smem + OFF_BUF);
    float* rs = rv + BM * 8;
    int*   ri = reinterpret_cast<int*>(rs + BM * 8);
    if (wid < 4) {
#pragma unroll
        for (int i = 0; i < 4; i++) {
            int r = lane + 32 * i;
            rv[r * 8 + wid] = v1[i];
            rs[r * 8 + wid] = v2[i];
            ri[r * 8 + wid] = i1[i];
        }
    } else {
        int slot = 4 + (wid & 1);
        rv[ar0 * 8 + slot] = v1[0]; rs[ar0 * 8 + slot] = v2[0]; ri[ar0 * 8 + slot] = i1[0];
        rv[ar1 * 8 + slot] = v1[1]; rs[ar1 * 8 + slot] = v2[1]; ri[ar1 * 8 + slot] = i1[1];
    }
    __syncthreads();

    if (tid < BM) {
        float bv = rv[tid * 8], bs = rs[tid * 8];
        int   bi = ri[tid * 8];
#pragma unroll
        for (int c = 1; c < 6; c++) {
            float ov = rv[tid * 8 + c], os = rs[tid * 8 + c];
            int   oi = ri[tid * 8 + c];
            if (ov < bv || (ov == bv && oi < bi)) {
                bs = fminf(bv, os); bv = ov; bi = oi;
            } else {
                bs = fminf(bs, ov);
            }
        }
        out[gn0 + tid] = (float)bi;            // fp32 output dtype
        float scmax = __int_as_float(g_scmax_i);
        float bound = 320.0f * sxs[tid] * scmax + 0.01f;
        if (bs - bv < bound) {
            int k = atomicAdd(&g_fixcount, 1);
            g_fixlist[k] = gn0 + tid;
        }
    }
}

// ---------------- exact fp32 fixup: 32 rows per block share one codebook sweep ----------------
#define FB 32
__global__ __launch_bounds__(TH)
void fixup_kernel(const float* __restrict__ x,
                  const float* __restrict__ cb,
                  float* __restrict__ out) {
    __shared__ float xr[FB][DIM];
    __shared__ int   rowid[FB];
    const int tid = threadIdx.x, lane = tid & 31, w = tid >> 5;
    const int nfix = g_fixcount;
    const int nb = (nfix + FB - 1) / FB;

    for (int b = blockIdx.x; b < nb; b += gridDim.x) {
        __syncthreads();
        if (tid < FB) {
            int fi = b * FB + tid;
            rowid[tid] = (fi < nfix) ? g_fixlist[fi] : -1;
        }
        __syncthreads();
#pragma unroll
        for (int u = 0; u < 2; u++) {
            int idx = u * TH + tid;            // over 32 rows x 16 float4
            int r = idx >> 4, q = idx & 15;
            int row = rowid[r];
            if (row < 0) row = rowid[0];       // rowid[0] always valid when nb>0
            *reinterpret_cast<float4*>(&xr[r][q * 4]) =
                __ldg(reinterpret_cast<const float4*>(x + (size_t)row * DIM + q * 4));
        }
        __syncthreads();

        // warp w owns rows 4w..4w+3; lane scans codes lane, lane+32, ...
        float bv[4] = {FLT_MAX, FLT_MAX, FLT_MAX, FLT_MAX};
        int   bi[4] = {0, 0, 0, 0};
        const int rr = w * 4;
        for (int j = lane; j < K_CODES; j += 32) {
            const float4* c4 = reinterpret_cast<const float4*>(cb + (size_t)j * DIM);
            float d0 = 0.f, d1 = 0.f, d2 = 0.f, d3 = 0.f;
#pragma unroll
            for (int q = 0; q < 16; q++) {
                float4 cv = __ldg(c4 + q);
                float4 x0 = *reinterpret_cast<const float4*>(&xr[rr + 0][q * 4]);
                float4 x1 = *reinterpret_cast<const float4*>(&xr[rr + 1][q * 4]);
                float4 x2 = *reinterpret_cast<const float4*>(&xr[rr + 2][q * 4]);
                float4 x3 = *reinterpret_cast<const float4*>(&xr[rr + 3][q * 4]);
                d0 = fmaf(x0.x, cv.x, d0); d0 = fmaf(x0.y, cv.y, d0);
                d0 = fmaf(x0.z, cv.z, d0); d0 = fmaf(x0.w, cv.w, d0);
                d1 = fmaf(x1.x, cv.x, d1); d1 = fmaf(x1.y, cv.y, d1);
                d1 = fmaf(x1.z, cv.z, d1); d1 = fmaf(x1.w, cv.w, d1);
                d2 = fmaf(x2.x, cv.x, d2); d2 = fmaf(x2.y, cv.y, d2);
                d2 = fmaf(x2.z, cv.z, d2); d2 = fmaf(x2.w, cv.w, d2);
                d3 = fmaf(x3.x, cv.x, d3); d3 = fmaf(x3.y, cv.y, d3);
                d3 = fmaf(x3.z, cv.z, d3); d3 = fmaf(x3.w, cv.w, d3);
            }
            float cqv = __ldg(&g_csq[j]);
            float t0 = fmaf(-2.f, d0, cqv), t1 = fmaf(-2.f, d1, cqv);
            float t2 = fmaf(-2.f, d2, cqv), t3 = fmaf(-2.f, d3, cqv);
            if (t0 < bv[0]) { bv[0] = t0; bi[0] = j; }
            if (t1 < bv[1]) { bv[1] = t1; bi[1] = j; }
            if (t2 < bv[2]) { bv[2] = t2; bi[2] = j; }
            if (t3 < bv[3]) { bv[3] = t3; bi[3] = j; }
        }
        // lexicographic lane merge (first-min semantics)
#pragma unroll
        for (int d = 1; d < 32; d <<= 1) {
#pragma unroll
            for (int r = 0; r < 4; r++) {
                float ov = __shfl_xor_sync(0xffffffffu, bv[r], d);
                int   oi = __shfl_xor_sync(0xffffffffu, bi[r], d);
                if (ov < bv[r] || (ov == bv[r] && oi < bi[r])) { bv[r] = ov; bi[r] = oi; }
            }
        }
        if (lane == 0) {
#pragma unroll
            for (int r = 0; r < 4; r++) {
                int row = rowid[rr + r];
                if (row >= 0) out[row] = (float)bi[r];
            }
        }
        __syncthreads();
    }
}

extern "C" void kernel_launch(void* const* d_in, const int* in_sizes, int n_in,
                              void* d_out, int out_size) {
    const float* x  = (const float*)d_in[0];
    const float* cb = (const float*)d_in[1];
    if (n_in >= 2 && in_sizes[0] == K_CODES * DIM && in_sizes[1] == N_ROWS * DIM) {
        const float* t = x; x = cb; cb = t;
    }
    float* out = (float*)d_out;

    cudaFuncSetAttribute(vq_kernel, cudaFuncAttributeMaxDynamicSharedMemorySize, SMEM_SZ);
    pack_cb_kernel<<<K_CODES / TH, TH>>>(cb);
    vq_kernel<<<N_ROWS / BM, TH, SMEM_SZ>>>(x, cb, out);
    fixup_kernel<<<64, TH>>>(x, cb, out);
}

// round 14
// speedup vs baseline: 1.0838x; 1.0838x over previous
#include <cuda_runtime.h>
#include <stdint.h>
#include <float.h>

#define N_ROWS   32768
#define K_CODES  8192
#define DIM      64
#define TH       256
#define BM       128
#define NT       128              // tiles of 64 codes (32 exact + 32 approx)

// ---- smem layout (bytes) ----
#define OFF_XS   0                // float2 xs[128][34] (272B/row, float4-aligned) 34816
#define OFF_XQ   34816            // int4  xq[128][9]  (144B/row)                18432
#define OFF_SX   53248            // float sxs[128]                                512
#define OFF_FIX  53760            // int fixn; int fixlist[128]                    544
#define OFF_BUF  54528            // 2 x 12800 double-buffered tile
#define BUF_B    12800            // 8192 exact fp32 + 4096 packed + 512 meta
#define SMEM_SZ  (OFF_BUF + 2 * BUF_B)   // 80128

// ---- device globals ----
__device__ int4  g_cq[K_CODES * 8];   // per code, per 8-dim group: (hi0-3, lo0-3, hi4-7, lo4-7)
__device__ float g_csq[K_CODES];
__device__ float g_scd[K_CODES];      // sc / 126  (dist = csq - sx*scd*I)
__device__ int   g_scmax_i = 0;       // atomicMax of sc bits (idempotent across calls)

__device__ __forceinline__ int pack4(int b0, int b1, int b2, int b3) {
    return (b0 & 0xff) | ((b1 & 0xff) << 8) | ((b2 & 0xff) << 16) | ((b3 & 0xff) << 24);
}
__device__ __forceinline__ uint32_t smem_u32(const void* p) {
    uint32_t a;
    asm("{ .reg .u64 t; cvta.to.shared.u64 t, %1; cvt.u32.u64 %0, t; }" : "=r"(a) : "l"(p));
    return a;
}
__device__ __forceinline__ void cp16(uint32_t dst, const void* src) {
    asm volatile("cp.async.ca.shared.global [%0], [%1], 16;" :: "r"(dst), "l"(src) : "memory");
}
#define CP_COMMIT() asm volatile("cp.async.commit_group;" ::: "memory")
#define CP_WAIT1()  asm volatile("cp.async.wait_group 1;" ::: "memory")
#define CP_WAIT0()  asm volatile("cp.async.wait_group 0;" ::: "memory")

// ---------------- pack codebook: int8 two-level split (lo scale 252) ----------------
__global__ void pack_cb_kernel(const float* __restrict__ cb) {
    int code = blockIdx.x * blockDim.x + threadIdx.x;
    if (code >= K_CODES) return;
    float f[DIM];
    const float4* c4 = reinterpret_cast<const float4*>(cb + (size_t)code * DIM);
#pragma unroll
    for (int i = 0; i < 16; i++) *reinterpret_cast<float4*>(f + 4 * i) = c4[i];
    float s = 0.f, mx = 0.f;
#pragma unroll
    for (int d = 0; d < DIM; d++) { s = fmaf(f[d], f[d], s); mx = fmaxf(mx, fabsf(f[d])); }
    float sc  = fmaxf(mx, 1e-30f) * (1.0f / 127.0f);
    float inv = 1.0f / sc;
#pragma unroll
    for (int g = 0; g < 8; g++) {
        int h[8], l[8];
#pragma unroll
        for (int t = 0; t < 8; t++) {
            float v = f[8 * g + t] * inv;
            h[t] = __float2int_rn(v);
            l[t] = __float2int_rn((v - (float)h[t]) * 252.0f);
        }
        g_cq[code * 8 + g] = make_int4(pack4(h[0], h[1], h[2], h[3]),
                                       pack4(l[0], l[1], l[2], l[3]),
                                       pack4(h[4], h[5], h[6], h[7]),
                                       pack4(l[4], l[5], l[6], l[7]));
    }
    g_csq[code] = s;
    g_scd[code] = sc * (1.0f / 126.0f);
    atomicMax(&g_scmax_i, __float_as_int(sc));
}

// ---------------- tile fill: exact fp32 + packed + meta ----------------
__device__ __forceinline__ void fill_tile(int t, uint32_t bufb, int tid,
                                          const float* __restrict__ cb) {
    // exact fp32: codes [t*64, t*64+32), 32 x 256B = 512 chunks
#pragma unroll
    for (int u = 0; u < 2; u++) {
        int idx = u * TH + tid;
        int c = idx >> 4, q = idx & 15;
        cp16(bufb + c * 256 + q * 16, cb + (size_t)(t * 64 + c) * DIM + q * 4);
    }
    // packed: codes [t*64+32, t*64+64), 32 x 128B = 256 chunks
    {
        int c = tid >> 3, h = tid & 7;
        cp16(bufb + 8192 + c * 128 + h * 16, g_cq + (size_t)(t * 64 + 32 + c) * 8 + h);
    }
    // meta: csq[64] @ +12288, scd[32] @ +12544
    if (tid < 16)
        cp16(bufb + 12288 + tid * 16, g_csq + t * 64 + tid * 4);
    else if (tid < 24)
        cp16(bufb + 12544 + (tid - 16) * 16, g_scd + t * 64 + 32 + (tid - 16) * 4);
}

// ---------------- main kernel: dual-pipe + integrated exact fixup ----------------
__global__ __launch_bounds__(TH, 2)
void vq_kernel(const float* __restrict__ x,
               const float* __restrict__ cb,
               float* __restrict__ out) {
    extern __shared__ char smem[];
    const uint32_t sb = smem_u32(smem);
    float* sxs    = reinterpret_cast<float*>(smem + OFF_SX);
    int*   fixn   = reinterpret_cast<int*>(smem + OFF_FIX);
    int*   fixlist= fixn + 4;

    const int tid  = threadIdx.x;
    const int lane = tid & 31;
    const int wid  = tid >> 5;
    const int gn0  = blockIdx.x * BM;

    // ---- fill x tile (coalesced float4) ----
    {
        const float4* gx = reinterpret_cast<const float4*>(x + (size_t)gn0 * DIM);
#pragma unroll
        for (int u = 0; u < 8; u++) {
            int idx = u * TH + tid;
            int row = idx >> 4, pp = idx & 15;
            *reinterpret_cast<float4*>(smem + OFF_XS + row * 272 + pp * 16) = __ldg(gx + idx);
        }
    }
    if (tid == 0) fixn[0] = 0;
    __syncthreads();

    // ---- quantize x rows (one thread per row) ----
    if (tid < BM) {
        const char* xr = smem + OFF_XS + tid * 272;
        float f[16][4];
        float mx = 0.f;
#pragma unroll
        for (int q = 0; q < 16; q++) {
            float4 v = *reinterpret_cast<const float4*>(xr + q * 16);
            f[q][0] = v.x; f[q][1] = v.y; f[q][2] = v.z; f[q][3] = v.w;
            mx = fmaxf(mx, fmaxf(fmaxf(fabsf(v.x), fabsf(v.y)), fmaxf(fabsf(v.z), fabsf(v.w))));
        }
        float sx  = fmaxf(mx, 1e-30f) * (1.0f / 127.0f);
        float inv = 1.0f / sx;
        sxs[tid] = sx;
#pragma unroll
        for (int g = 0; g < 8; g++) {
            int h[8], l[8];
#pragma unroll
            for (int t2 = 0; t2 < 8; t2++) {
                float v = f[2 * g + (t2 >> 2)][t2 & 3] * inv;
                h[t2] = __float2int_rn(v);
                l[t2] = __float2int_rn((v - (float)h[t2]) * 252.0f);
            }
            *reinterpret_cast<int4*>(smem + OFF_XQ + tid * 144 + g * 16) =
                make_int4(pack4(h[0], h[1], h[2], h[3]), pack4(l[0], l[1], l[2], l[3]),
                          pack4(h[4], h[5], h[6], h[7]), pack4(l[4], l[5], l[6], l[7]));
        }
    }
    __syncthreads();

    // approx-warp persistent state
    int4 X[8];
    float asx = 0.f;
    int arow = 0;
    if (wid >= 4) {
        arow = (wid - 4) * 32 + lane;
#pragma unroll
        for (int g = 0; g < 8; g++)
            X[g] = *reinterpret_cast<const int4*>(smem + OFF_XQ + arow * 144 + g * 16);
        asx = sxs[arow];
    }

    // running argmin state: exact warps use [0..3] (subrows), approx use [0]
    float v1[4] = {FLT_MAX, FLT_MAX, FLT_MAX, FLT_MAX};
    float v2[4] = {FLT_MAX, FLT_MAX, FLT_MAX, FLT_MAX};
    int   i1[4] = {0, 0, 0, 0};

    fill_tile(0, sb + OFF_BUF, tid, cb);
    CP_COMMIT();

    for (int t = 0; t < NT; t++) {
        const int s = t & 1;
        if (t) __syncthreads();
        if (t + 1 < NT) {
            fill_tile(t + 1, sb + OFF_BUF + (s ^ 1) * BUF_B, tid, cb);
            CP_COMMIT();
            CP_WAIT1();
        } else {
            CP_WAIT0();
        }
        __syncthreads();

        const char* buf = smem + OFF_BUF + s * BUF_B;
        if (wid < 4) {
            // ======== exact fp32: 8 codes per warp, 4 subrows per lane ========
            const int ec0 = wid * 8;
            float acc[4][8];
#pragma unroll
            for (int i = 0; i < 4; i++)
#pragma unroll
                for (int j = 0; j < 8; j++) acc[i][j] = 0.f;
#pragma unroll 4
            for (int pp = 0; pp < 16; pp++) {
                float4 a[4];
#pragma unroll
                for (int i = 0; i < 4; i++)
                    a[i] = *reinterpret_cast<const float4*>(
                        smem + OFF_XS + (lane + 32 * i) * 272 + pp * 16);
#pragma unroll
                for (int j = 0; j < 8; j++) {
                    float4 b = *reinterpret_cast<const float4*>(buf + (ec0 + j) * 256 + pp * 16);
#pragma unroll
                    for (int i = 0; i < 4; i++) {
                        acc[i][j] = fmaf(a[i].x, b.x, acc[i][j]);
                        acc[i][j] = fmaf(a[i].y, b.y, acc[i][j]);
                        acc[i][j] = fmaf(a[i].z, b.z, acc[i][j]);
                        acc[i][j] = fmaf(a[i].w, b.w, acc[i][j]);
                    }
                }
            }
#pragma unroll
            for (int j = 0; j < 8; j++) {
                int gk = t * 64 + ec0 + j;
                float cqv = *reinterpret_cast<const float*>(buf + 12288 + (ec0 + j) * 4);
#pragma unroll
                for (int i = 0; i < 4; i++) {
                    float d = fmaf(-2.f, acc[i][j], cqv);
                    if (d < v1[i]) { v2[i] = v1[i]; v1[i] = d; i1[i] = gk; }
                    else if (d < v2[i]) v2[i] = d;
                }
            }
        } else {
            // ======== approx dp4a: 32 codes, one row per lane ========
#pragma unroll 2
            for (int c = 0; c < 32; c++) {
                int hh = 0, hl = 0, lh = 0;
#pragma unroll
                for (int g = 0; g < 8; g++) {
                    int4 cg = *reinterpret_cast<const int4*>(buf + 8192 + c * 128 + g * 16);
                    hh = __dp4a(X[g].x, cg.x, hh);
                    hl = __dp4a(X[g].x, cg.y, hl);
                    lh = __dp4a(X[g].y, cg.x, lh);
                    hh = __dp4a(X[g].z, cg.z, hh);
                    hl = __dp4a(X[g].z, cg.w, hl);
                    lh = __dp4a(X[g].w, cg.z, lh);
                }
                int I = hh * 252 + hl + lh;
                float cqv = *reinterpret_cast<const float*>(buf + 12288 + (32 + c) * 4);
                float scd = *reinterpret_cast<const float*>(buf + 12544 + c * 4);
                float d = fmaf(-asx * scd, (float)I, cqv);
                int gk = t * 64 + 32 + c;
                if (d < v1[0]) { v2[0] = v1[0]; v1[0] = d; i1[0] = gk; }
                else if (d < v2[0]) v2[0] = d;
            }
        }
    }

    // ---- merge 5 slots per row (4 exact warps + owning approx warp) ----
    __syncthreads();
    float* rv = reinterpret_cast<float*>(smem + OFF_BUF);
    float* rs = rv + BM * 8;
    int*   ri = reinterpret_cast<int*>(rs + BM * 8);
    if (wid < 4) {
#pragma unroll
        for (int i = 0; i < 4; i++) {
            int r = lane + 32 * i;
            rv[r * 8 + wid] = v1[i]; rs[r * 8 + wid] = v2[i]; ri[r * 8 + wid] = i1[i];
        }
    } else {
        rv[arow * 8 + 4] = v1[0]; rs[arow * 8 + 4] = v2[0]; ri[arow * 8 + 4] = i1[0];
    }
    __syncthreads();

    if (tid < BM) {
        float bv = rv[tid * 8], bs = rs[tid * 8];
        int   bi = ri[tid * 8];
#pragma unroll
        for (int c = 1; c < 5; c++) {
            float ov = rv[tid * 8 + c], os = rs[tid * 8 + c];
            int   oi = ri[tid * 8 + c];
            if (ov < bv || (ov == bv && oi < bi)) { bs = fminf(bv, os); bv = ov; bi = oi; }
            else bs = fminf(bs, ov);
        }
        out[gn0 + tid] = (float)bi;
        float scmax = __int_as_float(g_scmax_i);
        float bound = 200.0f * sxs[tid] * scmax + 1e-3f;   // 2x dist-error bound (lo=252)
        if (bs - bv < bound) {
            int k = atomicAdd(fixn, 1);
            fixlist[k] = tid;
        }
    }
    __syncthreads();

    // ---- integrated exact fp32 fixup for flagged rows ----
    const int nf = fixn[0];
    float* sv = reinterpret_cast<float*>(smem + OFF_BUF);
    int*   si = reinterpret_cast<int*>(sv + TH);
    for (int f = 0; f < nf; f++) {
        const int row = fixlist[f];
        const char* xr = smem + OFF_XS + row * 272;
        float bv = FLT_MAX; int bi = 0;
#pragma unroll 1
        for (int cc = 0; cc < 32; cc++) {
            int j = cc * TH + tid;
            const float4* c4 = reinterpret_cast<const float4*>(cb + (size_t)j * DIM);
            float dot = 0.f;
#pragma unroll
            for (int q = 0; q < 16; q++) {
                float4 cv = __ldg(c4 + q);
                float4 xv = *reinterpret_cast<const float4*>(xr + q * 16);
                dot = fmaf(xv.x, cv.x, dot); dot = fmaf(xv.y, cv.y, dot);
                dot = fmaf(xv.z, cv.z, dot); dot = fmaf(xv.w, cv.w, dot);
            }
            float d = fmaf(-2.f, dot, __ldg(&g_csq[j]));
            if (d < bv) { bv = d; bi = j; }   // j ascending per thread -> first-min
        }
        __syncthreads();                       // sv/si free (prev iter done)
        sv[tid] = bv; si[tid] = bi;
        __syncthreads();
        for (int st = TH / 2; st > 0; st >>= 1) {
            if (tid < st) {
                float ov = sv[tid + st]; int oi = si[tid + st];
                if (ov < sv[tid] || (ov == sv[tid] && oi < si[tid])) { sv[tid] = ov; si[tid] = oi; }
            }
            __syncthreads();
        }
        if (tid == 0) out[gn0 + row] = (float)si[0];
    }
}

extern "C" void kernel_launch(void* const* d_in, const int* in_sizes, int n_in,
                              void* d_out, int out_size) {
    const float* x  = (const float*)d_in[0];
    const float* cb = (const float*)d_in[1];
    if (n_in >= 2 && in_sizes[0] == K_CODES * DIM && in_sizes[1] == N_ROWS * DIM) {
        const float* t = x; x = cb; cb = t;
    }
    float* out = (float*)d_out;

    cudaFuncSetAttribute(vq_kernel, cudaFuncAttributeMaxDynamicSharedMemorySize, SMEM_SZ);
    pack_cb_kernel<<<K_CODES / TH, TH>>>(cb);
    vq_kernel<<<N_ROWS / BM, TH, SMEM_SZ>>>(x, cb, out);
}

// round 15
// speedup vs baseline: 2.5259x; 2.3306x over previous
#include <cuda_runtime.h>
#include <stdint.h>
#include <float.h>

#define N_ROWS   32768
#define K_CODES  8192
#define DIM      64
#define DP       32           // 8-byte d-pairs per row
#define BM       128          // rows per CTA
#define BK       32           // codes per k-tile
#define TH       256
#define NT       (K_CODES / BK)   // 256 tiles

__device__ float g_csq[K_CODES];

__global__ void csq_kernel(const float* __restrict__ cb) {
    int k = blockIdx.x * blockDim.x + threadIdx.x;
    if (k >= K_CODES) return;
    const float4* row = reinterpret_cast<const float4*>(cb + (size_t)k * DIM);
    float s = 0.f;
#pragma unroll
    for (int i = 0; i < DIM / 4; i++) {
        float4 v = row[i];
        s = fmaf(v.x, v.x, s); s = fmaf(v.y, v.y, s);
        s = fmaf(v.z, v.z, s); s = fmaf(v.w, v.w, s);
    }
    g_csq[k] = s;
}

// Packed f32x2 FMA: d = a*b + d on (lo,hi) fp32 pairs. Validated exact in R5 (rel_err 0).
__device__ __forceinline__ void ffma2(unsigned long long& d,
                                      unsigned long long a,
                                      unsigned long long b) {
    asm("fma.rn.f32x2 %0, %1, %2, %0;" : "+l"(d) : "l"(a), "l"(b));
}
__device__ __forceinline__ unsigned long long pack2(float lo, float hi) {
    unsigned long long r;
    asm("mov.b64 %0, {%1, %2};" : "=l"(r) : "f"(lo), "f"(hi));
    return r;
}
__device__ __forceinline__ void unpack2(unsigned long long v, float& lo, float& hi) {
    asm("mov.b64 {%0, %1}, %2;" : "=f"(lo), "=f"(hi) : "l"(v));
}

__global__ __launch_bounds__(TH, 2)
void vq_kernel(const float* __restrict__ x,
               const float* __restrict__ cb,
               float* __restrict__ out) {
    // Transposed tiles (d-pair major). 32KB + 2*8KB = 48KB static.
    __shared__ unsigned long long xs[DP * BM];        // xs[p][row]
    __shared__ unsigned long long cs[2][DP * BK];     // cs[buf][p][c]

    const int tid    = threadIdx.x;
    const int lane   = tid & 31;
    const int w      = tid >> 5;          // warp 0..7 -> 16-row block
    const int colgrp = lane & 7;          // column lane
    const int rg     = lane >> 3;         // row sub-block 0..3
    const int row0   = w * 16 + rg * 4;   // this thread's 4 contiguous rows
    const int gn0    = blockIdx.x * BM;

    // ---- fill x tile: xs[p][row] (conflict-free smem writes) ----
    {
        const float4* gx4 = reinterpret_cast<const float4*>(x);
#pragma unroll
        for (int u = 0; u < 8; u++) {
            int idx = u * TH + tid;
            int row = idx & (BM - 1);
            int pp  = idx >> 7;                       // 0..15 float4 index
            float4 v = __ldg(&gx4[(size_t)(gn0 + row) * (DIM / 4) + pp]);
            xs[(2 * pp)     * BM + row] = pack2(v.x, v.y);
            xs[(2 * pp + 1) * BM + row] = pack2(v.z, v.w);
        }
    }

    const float4* gc4 = reinterpret_cast<const float4*>(cb);
    const int pc = tid & 31;              // code within tile (fill role)
    const int pq = tid >> 5;              // 0..7 float4 index (fill role)

    // ---- stage tile 0 directly ----
    {
        float4 v0 = __ldg(&gc4[(size_t)pc * 16 + pq]);
        float4 v1 = __ldg(&gc4[(size_t)pc * 16 + pq + 8]);
        cs[0][(2 * pq)           * BK + pc] = pack2(v0.x, v0.y);
        cs[0][(2 * pq + 1)       * BK + pc] = pack2(v0.z, v0.w);
        cs[0][(2 * (pq + 8))     * BK + pc] = pack2(v1.x, v1.y);
        cs[0][(2 * (pq + 8) + 1) * BK + pc] = pack2(v1.z, v1.w);
    }
    __syncthreads();

    float best[4];
    int   bidx[4];
#pragma unroll
    for (int i = 0; i < 4; i++) { best[i] = FLT_MAX; bidx[i] = 0; }

    for (int t = 0; t < NT; t++) {
        const int s = t & 1;
        const bool pre = (t + 1 < NT);
        float4 pv0, pv1;
        if (pre) {
            size_t base = (size_t)((t + 1) * BK + pc) * 16;
            pv0 = __ldg(&gc4[base + pq]);
            pv1 = __ldg(&gc4[base + pq + 8]);
        }

        // ---- main FFMA2 loop: 4 rows x 4 cols packed accumulators ----
        unsigned long long acc[16];
#pragma unroll
        for (int i = 0; i < 16; i++) acc[i] = 0ull;

        const unsigned long long* csb = cs[s];
#pragma unroll
        for (int p = 0; p < DP; p++) {
            unsigned long long a0 = xs[p * BM + row0];
            unsigned long long a1 = xs[p * BM + row0 + 1];
            unsigned long long a2 = xs[p * BM + row0 + 2];
            unsigned long long a3 = xs[p * BM + row0 + 3];
            unsigned long long b0 = csb[p * BK + colgrp];
            unsigned long long b1 = csb[p * BK + 8 + colgrp];
            unsigned long long b2 = csb[p * BK + 16 + colgrp];
            unsigned long long b3 = csb[p * BK + 24 + colgrp];
            ffma2(acc[0],  a0, b0); ffma2(acc[1],  a0, b1);
            ffma2(acc[2],  a0, b2); ffma2(acc[3],  a0, b3);
            ffma2(acc[4],  a1, b0); ffma2(acc[5],  a1, b1);
            ffma2(acc[6],  a1, b2); ffma2(acc[7],  a1, b3);
            ffma2(acc[8],  a2, b0); ffma2(acc[9],  a2, b1);
            ffma2(acc[10], a2, b2); ffma2(acc[11], a2, b3);
            ffma2(acc[12], a3, b0); ffma2(acc[13], a3, b1);
            ffma2(acc[14], a3, b2); ffma2(acc[15], a3, b3);
        }

        // ---- epilogue: dist = csq - 2*dot; per-row ascending j => first-min kept ----
        const int gkbase = t * BK + colgrp;
#pragma unroll
        for (int j = 0; j < 4; j++) {
            float cq = __ldg(&g_csq[gkbase + 8 * j]);
            const int gk = gkbase + 8 * j;
#pragma unroll
            for (int i = 0; i < 4; i++) {
                float lo, hi;
                unpack2(acc[i * 4 + j], lo, hi);
                float d = fmaf(-2.f, lo + hi, cq);
                if (d < best[i]) { best[i] = d; bidx[i] = gk; }
            }
        }

        // ---- store prefetched tile into the other buffer ----
        if (pre) {
            unsigned long long* dst = cs[s ^ 1];
            dst[(2 * pq)           * BK + pc] = pack2(pv0.x, pv0.y);
            dst[(2 * pq + 1)       * BK + pc] = pack2(pv0.z, pv0.w);
            dst[(2 * (pq + 8))     * BK + pc] = pack2(pv1.x, pv1.y);
            dst[(2 * (pq + 8) + 1) * BK + pc] = pack2(pv1.z, pv1.w);
        }
        __syncthreads();
    }

    // ---- merge the 8 colgrp lanes (lexicographic => global first-min) ----
#pragma unroll
    for (int d = 1; d < 8; d <<= 1) {
#pragma unroll
        for (int i = 0; i < 4; i++) {
            float ov = __shfl_xor_sync(0xffffffffu, best[i], d);
            int   oi = __shfl_xor_sync(0xffffffffu, bidx[i], d);
            if (ov < best[i] || (ov == best[i] && oi < bidx[i])) {
                best[i] = ov; bidx[i] = oi;
            }
        }
    }
    if (colgrp == 0) {
#pragma unroll
        for (int i = 0; i < 4; i++)
            out[gn0 + row0 + i] = (float)bidx[i];     // fp32 output dtype
    }
}

extern "C" void kernel_launch(void* const* d_in, const int* in_sizes, int n_in,
                              void* d_out, int out_size) {
    const float* x  = (const float*)d_in[0];
    const float* cb = (const float*)d_in[1];
    if (n_in >= 2 && in_sizes[0] == K_CODES * DIM && in_sizes[1] == N_ROWS * DIM) {
        const float* t = x; x = cb; cb = t;
    }
    float* out = (float*)d_out;

    csq_kernel<<<K_CODES / 256, 256>>>(cb);
    vq_kernel<<<N_ROWS / BM, TH>>>(x, cb, out);
}

// round 16
// speedup vs baseline: 2.9916x; 1.1844x over previous
#include <cuda_runtime.h>
#include <stdint.h>
#include <float.h>

#define N_ROWS   32768
#define K_CODES  8192
#define DIM      64
#define DP       32               // 8-byte d-pairs per code/row
#define BM       256              // rows per CTA
#define BK       64               // codes per tile
#define TH       256
#define NT       (K_CODES / BK)   // 128 tiles
#define CSTR     65               // cs row stride in u64 (pad 1 -> conflict-free STS)
#define XS_U64   (DP * BM)        // 8192
#define CS_U64   (DP * CSTR)      // 2080 per buffer
#define SMEM_U64 (XS_U64 + 2 * CS_U64)   // 12352 u64 = 98816 B

__device__ float g_csq[K_CODES];

__global__ void csq_kernel(const float* __restrict__ cb) {
    int k = blockIdx.x * blockDim.x + threadIdx.x;
    if (k >= K_CODES) return;
    const float4* row = reinterpret_cast<const float4*>(cb + (size_t)k * DIM);
    float s = 0.f;
#pragma unroll
    for (int i = 0; i < DIM / 4; i++) {
        float4 v = row[i];
        s = fmaf(v.x, v.x, s); s = fmaf(v.y, v.y, s);
        s = fmaf(v.z, v.z, s); s = fmaf(v.w, v.w, s);
    }
    g_csq[k] = s;
}

// Packed f32x2 FMA (validated exact; rel_err 0 in R5/R15)
__device__ __forceinline__ void ffma2(unsigned long long& d,
                                      unsigned long long a,
                                      unsigned long long b) {
    asm("fma.rn.f32x2 %0, %1, %2, %0;" : "+l"(d) : "l"(a), "l"(b));
}
__device__ __forceinline__ unsigned long long pack2(float lo, float hi) {
    unsigned long long r;
    asm("mov.b64 %0, {%1, %2};" : "=l"(r) : "f"(lo), "f"(hi));
    return r;
}
__device__ __forceinline__ void unpack2(unsigned long long v, float& lo, float& hi) {
    asm("mov.b64 {%0, %1}, %2;" : "=f"(lo), "=f"(hi) : "l"(v));
}

__global__ __launch_bounds__(TH, 1)
void vq_kernel(const float* __restrict__ x,
               const float* __restrict__ cb,
               float* __restrict__ out) {
    extern __shared__ unsigned long long sm[];
    unsigned long long* xs  = sm;                    // xs[p*BM + row]
    unsigned long long* cs0 = sm + XS_U64;           // cs[buf][p*CSTR + c]

    const int tid  = threadIdx.x;
    const int lane = tid & 31;
    const int w    = tid >> 5;           // warp 0..7 -> cols w*8..w*8+7 of each tile
    const int gn0  = blockIdx.x * BM;

    // ---- fill x tile (transposed, conflict-free STS; global reads 2 lanes/sector) ----
    {
        const float4* gx4 = reinterpret_cast<const float4*>(x);
#pragma unroll
        for (int u = 0; u < 16; u++) {
            int idx = u * TH + tid;
            int row = idx & (BM - 1);
            int pp  = idx >> 8;                      // 0..15 float4 index
            float4 v = __ldg(&gx4[(size_t)(gn0 + row) * 16 + pp]);
            xs[(2 * pp)     * BM + row] = pack2(v.x, v.y);
            xs[(2 * pp + 1) * BM + row] = pack2(v.z, v.w);
        }
    }

    // tile-fill role: 4 threads per code
    const int fc = tid & 63;             // code within tile
    const int fq = tid >> 6;             // 0..3

    const float4* gc4 = reinterpret_cast<const float4*>(cb);
    // ---- stage tile 0 ----
    {
#pragma unroll
        for (int u = 0; u < 4; u++) {
            int q = fq * 4 + u;
            float4 v = __ldg(&gc4[(size_t)fc * 16 + q]);
            cs0[(2 * q)     * CSTR + fc] = pack2(v.x, v.y);
            cs0[(2 * q + 1) * CSTR + fc] = pack2(v.z, v.w);
        }
    }
    __syncthreads();

    float best[8];
    int   bidx[8];
#pragma unroll
    for (int i = 0; i < 8; i++) { best[i] = FLT_MAX; bidx[i] = 0; }

    for (int t = 0; t < NT; t++) {
        const int s = t & 1;
        const bool pre = (t + 1 < NT);
        float4 pv[4];
        if (pre) {
            size_t base = (size_t)((t + 1) * BK + fc) * 16;
#pragma unroll
            for (int u = 0; u < 4; u++) pv[u] = __ldg(&gc4[base + fq * 4 + u]);
        }

        // ---- main loop: 8 rows x 8 cols packed accumulators ----
        unsigned long long acc[64];
#pragma unroll
        for (int i = 0; i < 64; i++) acc[i] = 0ull;

        const unsigned long long* csb = cs0 + s * CS_U64;
#pragma unroll 8
        for (int p = 0; p < DP; p++) {
            unsigned long long a[8], b[8];
#pragma unroll
            for (int i = 0; i < 8; i++) a[i] = xs[p * BM + lane + 32 * i];
#pragma unroll
            for (int j = 0; j < 8; j++) b[j] = csb[p * CSTR + w * 8 + j];   // warp-uniform bcast
#pragma unroll
            for (int i = 0; i < 8; i++)
#pragma unroll
                for (int j = 0; j < 8; j++) ffma2(acc[i * 8 + j], a[i], b[j]);
        }

        // ---- epilogue: dist = csq - 2*dot; ascending j per thread => first-min ----
        const int gk0 = t * BK + w * 8;
#pragma unroll
        for (int j = 0; j < 8; j++) {
            float cq = __ldg(&g_csq[gk0 + j]);
            const int gk = gk0 + j;
#pragma unroll
            for (int i = 0; i < 8; i++) {
                float lo, hi;
                unpack2(acc[i * 8 + j], lo, hi);
                float d = fmaf(-2.f, lo + hi, cq);
                if (d < best[i]) { best[i] = d; bidx[i] = gk; }
            }
        }

        // ---- store prefetched tile into the other buffer ----
        if (pre) {
            unsigned long long* dst = cs0 + (s ^ 1) * CS_U64;
#pragma unroll
            for (int u = 0; u < 4; u++) {
                int q = fq * 4 + u;
                dst[(2 * q)     * CSTR + fc] = pack2(pv[u].x, pv[u].y);
                dst[(2 * q + 1) * CSTR + fc] = pack2(pv[u].z, pv[u].w);
            }
        }
        __syncthreads();
    }

    // ---- cross-warp merge: 8 candidates per row, lexicographic => global first-min ----
    float* rv = reinterpret_cast<float*>(sm);            // [BM][8]  8KB
    int*   ri = reinterpret_cast<int*>(rv + BM * 8);     // [BM][8]  8KB (inside xs)
#pragma unroll
    for (int i = 0; i < 8; i++) {
        int r = lane + 32 * i;
        rv[r * 8 + w] = best[i];
        ri[r * 8 + w] = bidx[i];
    }
    __syncthreads();

    {
        int r = tid;                                     // one row per thread
        float bv = rv[r * 8];
        int   bi = ri[r * 8];
#pragma unroll
        for (int c = 1; c < 8; c++) {
            float ov = rv[r * 8 + c];
            int   oi = ri[r * 8 + c];
            if (ov < bv || (ov == bv && oi < bi)) { bv = ov; bi = oi; }
        }
        out[gn0 + r] = (float)bi;                        // fp32 output dtype
    }
}

extern "C" void kernel_launch(void* const* d_in, const int* in_sizes, int n_in,
                              void* d_out, int out_size) {
    const float* x  = (const float*)d_in[0];
    const float* cb = (const float*)d_in[1];
    if (n_in >= 2 && in_sizes[0] == K_CODES * DIM && in_sizes[1] == N_ROWS * DIM) {
        const float* t = x; x = cb; cb = t;
    }
    float* out = (float*)d_out;

    cudaFuncSetAttribute(vq_kernel, cudaFuncAttributeMaxDynamicSharedMemorySize,
                         SMEM_U64 * 8);
    csq_kernel<<<K_CODES / 256, 256>>>(cb);
    vq_kernel<<<N_ROWS / BM, TH, SMEM_U64 * 8>>>(x, cb, out);
}

// round 17
// speedup vs baseline: 3.3396x; 1.1163x over previous
#include <cuda_runtime.h>
#include <stdint.h>
#include <float.h>

#define N_ROWS   32768
#define K_CODES  8192
#define DIM      64
#define DP       32               // 8-byte d-pairs per code/row
#define BMC      224              // rows computed per CTA (7 per thread)
#define BK       64               // codes per tile
#define TH       256
#define NT       (K_CODES / BK)   // 128 tiles
#define CSTR     66               // cs row stride in u64 (even -> 16B-aligned pairs)
#define XS_U64   (DP * BMC)       // 7168
#define CS_U64   (DP * CSTR)      // 2112 per buffer
#define SMEM_U64 (XS_U64 + 2 * CS_U64)   // 11392 u64 = 91136 B
#define NCTA     148
#define NFULL    136              // first 136 CTAs own 224 real rows; last 12 own 192

__device__ float g_csq[K_CODES];

__global__ void csq_kernel(const float* __restrict__ cb) {
    int k = blockIdx.x * blockDim.x + threadIdx.x;
    if (k >= K_CODES) return;
    const float4* row = reinterpret_cast<const float4*>(cb + (size_t)k * DIM);
    float s = 0.f;
#pragma unroll
    for (int i = 0; i < DIM / 4; i++) {
        float4 v = row[i];
        s = fmaf(v.x, v.x, s); s = fmaf(v.y, v.y, s);
        s = fmaf(v.z, v.z, s); s = fmaf(v.w, v.w, s);
    }
    g_csq[k] = s;
}

// Packed f32x2 FMA (validated exact; rel_err 0 in R5/R15/R16)
__device__ __forceinline__ void ffma2(unsigned long long& d,
                                      unsigned long long a,
                                      unsigned long long b) {
    asm("fma.rn.f32x2 %0, %1, %2, %0;" : "+l"(d) : "l"(a), "l"(b));
}
__device__ __forceinline__ unsigned long long pack2(float lo, float hi) {
    unsigned long long r;
    asm("mov.b64 %0, {%1, %2};" : "=l"(r) : "f"(lo), "f"(hi));
    return r;
}
__device__ __forceinline__ void unpack2(unsigned long long v, float& lo, float& hi) {
    asm("mov.b64 {%0, %1}, %2;" : "=f"(lo), "=f"(hi) : "l"(v));
}

__global__ __launch_bounds__(TH, 1)
void vq_kernel(const float* __restrict__ x,
               const float* __restrict__ cb,
               float* __restrict__ out) {
    extern __shared__ unsigned long long sm[];
    unsigned long long* xs  = sm;               // xs[p*BMC + row]
    unsigned long long* cs0 = sm + XS_U64;      // cs[buf][p*CSTR + c]

    const int tid  = threadIdx.x;
    const int lane = tid & 31;
    const int w    = tid >> 5;                  // warp -> col group w*8
    const int b    = blockIdx.x;
    const int base  = (b < NFULL) ? b * BMC : NFULL * BMC + (b - NFULL) * 192;
    const int nrows = (b < NFULL) ? BMC : 192;

    // ---- fill x tile (rows >= nrows clamp-read; masked on output) ----
    {
        const float4* gx4 = reinterpret_cast<const float4*>(x);
#pragma unroll
        for (int u = 0; u < 14; u++) {          // 224 rows x 16 float4 = 3584
            int idx = u * TH + tid;
            int row = idx >> 4, pp = idx & 15;
            int gr  = base + min(row, nrows - 1);
            float4 v = __ldg(&gx4[(size_t)gr * 16 + pp]);
            xs[(2 * pp)     * BMC + row] = pack2(v.x, v.y);
            xs[(2 * pp + 1) * BMC + row] = pack2(v.z, v.w);
        }
    }

    // tile-fill role: 4 threads per code
    const int fc = tid & 63, fq = tid >> 6;
    const float4* gc4 = reinterpret_cast<const float4*>(cb);

    // ---- stage tile 0 ----
#pragma unroll
    for (int u = 0; u < 4; u++) {
        int q = fq * 4 + u;
        float4 v = __ldg(&gc4[(size_t)fc * 16 + q]);
        cs0[(2 * q)     * CSTR + fc] = pack2(v.x, v.y);
        cs0[(2 * q + 1) * CSTR + fc] = pack2(v.z, v.w);
    }
    __syncthreads();

    float best[7];
    int   bidx[7];
#pragma unroll
    for (int i = 0; i < 7; i++) { best[i] = FLT_MAX; bidx[i] = 0; }

    for (int t = 0; t < NT; t++) {
        const int s = t & 1;
        const bool pre = (t + 1 < NT);
        float4 pv[4];
        if (pre) {
            size_t gbase = (size_t)((t + 1) * BK + fc) * 16;
#pragma unroll
            for (int u = 0; u < 4; u++) pv[u] = __ldg(&gc4[gbase + fq * 4 + u]);
        }

        // ---- main loop: 7 rows x 8 cols packed accumulators ----
        unsigned long long acc[56];
#pragma unroll
        for (int i = 0; i < 56; i++) acc[i] = 0ull;

        const unsigned long long* csb = cs0 + s * CS_U64;
#pragma unroll 8
        for (int p = 0; p < DP; p++) {
            unsigned long long a[7], bb[8];
#pragma unroll
            for (int i = 0; i < 7; i++) a[i] = xs[p * BMC + lane + 32 * i];
#pragma unroll
            for (int j = 0; j < 4; j++) {       // 16B-aligned broadcast pair loads
                ulonglong2 bv = *reinterpret_cast<const ulonglong2*>(
                    &csb[p * CSTR + w * 8 + 2 * j]);
                bb[2 * j] = bv.x; bb[2 * j + 1] = bv.y;
            }
#pragma unroll
            for (int i = 0; i < 7; i++)
#pragma unroll
                for (int j = 0; j < 8; j++) ffma2(acc[i * 8 + j], a[i], bb[j]);
        }

        // ---- epilogue: tile-min via fminf tree, rare index recovery ----
        const int gk0 = t * BK + w * 8;
        float cq[8];
#pragma unroll
        for (int j = 0; j < 8; j++) cq[j] = __ldg(&g_csq[gk0 + j]);
#pragma unroll
        for (int i = 0; i < 7; i++) {
            float d[8];
#pragma unroll
            for (int j = 0; j < 8; j++) {
                float lo, hi;
                unpack2(acc[i * 8 + j], lo, hi);
                d[j] = fmaf(-2.f, lo + hi, cq[j]);
            }
            float m = fminf(fminf(fminf(d[0], d[1]), fminf(d[2], d[3])),
                            fminf(fminf(d[4], d[5]), fminf(d[6], d[7])));
            if (m < best[i]) {                  // strict <: earlier tile kept on ties
                best[i] = m;
                int jj = 7;
#pragma unroll
                for (int j = 6; j >= 0; j--)    // descending -> ends at FIRST j with d==m
                    if (d[j] == m) jj = j;
                bidx[i] = gk0 + jj;
            }
        }

        // ---- store prefetched tile ----
        if (pre) {
            unsigned long long* dst = cs0 + (s ^ 1) * CS_U64;
#pragma unroll
            for (int u = 0; u < 4; u++) {
                int q = fq * 4 + u;
                dst[(2 * q)     * CSTR + fc] = pack2(pv[u].x, pv[u].y);
                dst[(2 * q + 1) * CSTR + fc] = pack2(pv[u].z, pv[u].w);
            }
        }
        __syncthreads();
    }

    // ---- cross-warp merge: 8 candidates per row (lexicographic first-min) ----
    float* rv = reinterpret_cast<float*>(sm);            // [224][8]
    int*   ri = reinterpret_cast<int*>(rv + BMC * 8);    // [224][8]  (inside xs)
#pragma unroll
    for (int i = 0; i < 7; i++) {
        int r = lane + 32 * i;
        rv[r * 8 + w] = best[i];
        ri[r * 8 + w] = bidx[i];
    }
    __syncthreads();

    if (tid < BMC && tid < nrows) {
        float bv = rv[tid * 8];
        int   bi = ri[tid * 8];
#pragma unroll
        for (int c = 1; c < 8; c++) {
            float ov = rv[tid * 8 + c];
            int   oi = ri[tid * 8 + c];
            if (ov < bv || (ov == bv && oi < bi)) { bv = ov; bi = oi; }
        }
        out[base + tid] = (float)bi;                     // fp32 output dtype
    }
}

extern "C" void kernel_launch(void* const* d_in, const int* in_sizes, int n_in,
                              void* d_out, int out_size) {
    const float* x  = (const float*)d_in[0];
    const float* cb = (const float*)d_in[1];
    if (n_in >= 2 && in_sizes[0] == K_CODES * DIM && in_sizes[1] == N_ROWS * DIM) {
        const float* t = x; x = cb; cb = t;
    }
    float* out = (float*)d_out;

    cudaFuncSetAttribute(vq_kernel, cudaFuncAttributeMaxDynamicSharedMemorySize,
                         SMEM_U64 * 8);
    csq_kernel<<<K_CODES / 256, 256>>>(cb);
    vq_kernel<<<NCTA, TH, SMEM_U64 * 8>>>(x, cb, out);
}